// round 7
// baseline (speedup 1.0000x reference)
#include <cuda_runtime.h>
#include <math.h>

#define NN 8192
#define DD 64
#define LRALPHA 0.2f
#define CHUNK 32
#define NCHUNK 256    // NN / CHUNK
#define GROUP 32      // chunks per group
#define NGROUP 8      // NCHUNK / GROUP
#define NB 8192       // counting-sort bins
#define BR 8.0f       // fixed bin range [-BR, BR]
#define BININV 512.0f // NB / (2*BR)
#define MSTAB 8.0f    // softmax stabilizer (any fixed bound; exactness independent)

// ---------------- scratch (device globals; no allocation allowed) ----------------
__device__ float g_h[NN * DD];
__device__ float g_f1[NN];
__device__ float g_f2[NN];
__device__ float g_f2s[NN];             // f2 in bin-sorted order
__device__ int   g_perm[NN];            // sorted pos -> original row
__device__ float g_Eh[NN];              // exp(f2s - M)
__device__ float g_El[NN];              // exp(alpha*(f2s - M))
__device__ int g_cnt[NB];               // zero-init; k_binsort re-zeros each call
__device__ int g_off[NB + 1];
__device__ int g_tick;                  // ticket; last block of k_chunktot re-zeros
__device__ float g_ShC[NCHUNK * DD];    // per-chunk sums of Eh*h
__device__ float g_SlC[NCHUNK * DD];    // per-chunk sums of El*h
__device__ float g_ZhC[NCHUNK];
__device__ float g_ZlC[NCHUNK];
__device__ float g_GsufH[(NGROUP + 1) * DD];  // GsufH[g] = sum over groups >= g
__device__ float g_GpreL[(NGROUP + 1) * DD];  // GpreL[g] = sum over groups <  g
__device__ float g_GsufZh[NGROUP + 1];
__device__ float g_GpreZl[NGROUP + 1];

// monotone non-decreasing bin map, clamped (fixed range; consistency with the
// query side is all correctness needs — boundary bin is scanned exactly)
__device__ __forceinline__ int binof(float v) {
    int b = (int)((v + BR) * BININV);
    return min(max(b, 0), NB - 1);
}

// ---------------- K1: h = x@Wt (Wt column in registers), f1, f2, histogram ----------------
__global__ void __launch_bounds__(256) k_hf(
    const float* __restrict__ x, const float* __restrict__ Wt,
    const float* __restrict__ a1, const float* __restrict__ b1,
    const float* __restrict__ a2, const float* __restrict__ b2)
{
    __shared__ float sx[4][DD];
    __shared__ float sP[4][2][2];
    const int tid = threadIdx.x;
    const int r = tid >> 6;
    const int d = tid & 63;
    const int lane = d & 31;
    const int half = d >> 5;

    float W[DD];
#pragma unroll
    for (int k = 0; k < DD; k++) W[k] = Wt[k * DD + d];
    const float va1 = a1[d], va2 = a2[d];

#pragma unroll
    for (int g = 0; g < 4; g++) {
        const int row = blockIdx.x * 16 + g * 4 + r;
        __syncthreads();
        sx[r][d] = x[row * DD + d];
        __syncthreads();
        float acc = 0.f;
#pragma unroll
        for (int k = 0; k < DD; k++) acc = fmaf(sx[r][k], W[k], acc);
        g_h[row * DD + d] = acc;
        float p1 = acc * va1, p2 = acc * va2;
#pragma unroll
        for (int s = 16; s > 0; s >>= 1) {
            p1 += __shfl_down_sync(0xffffffffu, p1, s);
            p2 += __shfl_down_sync(0xffffffffu, p2, s);
        }
        if (lane == 0) { sP[r][half][0] = p1; sP[r][half][1] = p2; }
        __syncthreads();
        if (d == 0) {
            float f1 = sP[r][0][0] + sP[r][1][0] + b1[0];
            float f2 = sP[r][0][1] + sP[r][1][1] + b2[0];
            g_f1[row] = f1;
            g_f2[row] = f2;
            atomicAdd(&g_cnt[binof(f2)], 1);
        }
    }
}

// ---------------- K2: bin scan + state reset + fused scatter (1 block, 1024 thr) ----------------
__global__ void k_binsort() {
    __shared__ int sW[32];
    __shared__ int sFill[NB];           // 32 KB: running write cursors per bin
    const int tid = threadIdx.x;
    const int base = tid * 8;

    int4 ca = *(const int4*)&g_cnt[base];
    int4 cb = *(const int4*)&g_cnt[base + 4];
    int c[8] = {ca.x, ca.y, ca.z, ca.w, cb.x, cb.y, cb.z, cb.w};
    int s = 0;
#pragma unroll
    for (int j = 0; j < 8; j++) s += c[j];
    const int lane = tid & 31, w = tid >> 5;
    int v = s;
#pragma unroll
    for (int o = 1; o < 32; o <<= 1) {
        int n = __shfl_up_sync(0xffffffffu, v, o);
        if (lane >= o) v += n;
    }
    if (lane == 31) sW[w] = v;
    __syncthreads();
    if (w == 0) {
        int wv = sW[lane];
#pragma unroll
        for (int o = 1; o < 32; o <<= 1) {
            int n = __shfl_up_sync(0xffffffffu, wv, o);
            if (lane >= o) wv += n;
        }
        sW[lane] = wv;
    }
    __syncthreads();
    int excl = v - s + (w > 0 ? sW[w - 1] : 0);
#pragma unroll
    for (int j = 0; j < 8; j++) {
        g_off[base + j] = excl;
        sFill[base + j] = excl;        // cursor starts at bin offset
        excl += c[j];
    }
    if (tid == 1023) g_off[NB] = excl;

    // reset g_cnt for next replay
    const int4 z4 = make_int4(0, 0, 0, 0);
    *(int4*)&g_cnt[base] = z4; *(int4*)&g_cnt[base + 4] = z4;
    __syncthreads();

    // fused scatter: 8 rows per thread (coalesced reads)
#pragma unroll
    for (int j = 0; j < 8; j++) {
        const int i = tid + j * 1024;
        float f2 = g_f2[i];
        int b = binof(f2);
        int pos = atomicAdd(&sFill[b], 1);   // absolute position
        g_perm[pos] = i;
        g_f2s[pos] = f2;
        float f = f2 - MSTAB;
        g_Eh[pos] = expf(f);
        g_El[pos] = expf(LRALPHA * f);
    }
}

// ---------------- K3: per-chunk totals (fully parallel) + last-block group scan ----------------
__global__ void k_chunktot() {
    __shared__ float sA[4][DD], sB[4][DD], sZ[4][2];
    __shared__ float sGH[NGROUP][DD], sGL[NGROUP][DD];
    __shared__ float sGZh[NGROUP], sGZl[NGROUP];
    __shared__ int sLast;
    const int tid = threadIdx.x;       // 256
    const int q = tid >> 6;            // 0..3
    const int d = tid & 63;
    const int cblk = blockIdx.x;       // chunk id, 0..NCHUNK-1

    // 8 elements per (q,d) thread
    {
        const int jb = cblk * CHUNK + q * 8;
        float ah = 0.f, al = 0.f, zh = 0.f, zl = 0.f;
#pragma unroll
        for (int j = 0; j < 8; j++) {
            const int p = jb + j;
            float eh = g_Eh[p], el = g_El[p];
            float hv = g_h[g_perm[p] * DD + d];
            ah = fmaf(eh, hv, ah); al = fmaf(el, hv, al);
            zh += eh; zl += el;
        }
        sA[q][d] = ah; sB[q][d] = al;
        if (d == 0) { sZ[q][0] = zh; sZ[q][1] = zl; }
    }
    __syncthreads();
    if (q == 0) {
        g_ShC[cblk * DD + d] = sA[0][d] + sA[1][d] + sA[2][d] + sA[3][d];
        g_SlC[cblk * DD + d] = sB[0][d] + sB[1][d] + sB[2][d] + sB[3][d];
        if (d == 0) {
            g_ZhC[cblk] = sZ[0][0] + sZ[1][0] + sZ[2][0] + sZ[3][0];
            g_ZlC[cblk] = sZ[0][1] + sZ[1][1] + sZ[2][1] + sZ[3][1];
        }
    }
    __threadfence();                   // release this block's chunk totals
    __syncthreads();
    if (tid == 0) {
        int t = atomicAdd(&g_tick, 1);
        sLast = (t == NCHUNK - 1);
    }
    __syncthreads();
    if (!sLast) return;
    __threadfence();                   // acquire all blocks' totals

    // group sums: q handles groups {2q, 2q+1}
#pragma unroll
    for (int gg = 0; gg < 2; gg++) {
        const int g = q * 2 + gg;
        float sh = 0.f, sl = 0.f, szh = 0.f, szl = 0.f;
#pragma unroll 8
        for (int cc = 0; cc < GROUP; cc++) {
            const int c = g * GROUP + cc;
            sh += g_ShC[c * DD + d];
            sl += g_SlC[c * DD + d];
            if (d == 0) { szh += g_ZhC[c]; szl += g_ZlC[c]; }
        }
        sGH[g][d] = sh; sGL[g][d] = sl;
        if (d == 0) { sGZh[g] = szh; sGZl[g] = szl; }
    }
    __syncthreads();
    if (q == 0) {
        float suf = 0.f;
        g_GsufH[NGROUP * DD + d] = 0.f;
#pragma unroll
        for (int g = NGROUP - 1; g >= 0; g--) {
            suf += sGH[g][d];
            g_GsufH[g * DD + d] = suf;
        }
        float pre = 0.f;
#pragma unroll
        for (int g = 0; g < NGROUP; g++) {
            g_GpreL[g * DD + d] = pre;
            pre += sGL[g][d];
        }
        g_GpreL[NGROUP * DD + d] = pre;
        if (d == 0) {
            float sz = 0.f; g_GsufZh[NGROUP] = 0.f;
#pragma unroll
            for (int g = NGROUP - 1; g >= 0; g--) { sz += sGZh[g]; g_GsufZh[g] = sz; }
            float pz = 0.f;
#pragma unroll
            for (int g = 0; g < NGROUP; g++) { g_GpreZl[g] = pz; pz += sGZl[g]; }
            g_GpreZl[NGROUP] = pz;
            g_tick = 0;                // reset for next replay
        }
    }
}

// ---------------- K4: per-row 3-level suffix/prefix evaluation + ELU ----------------
__global__ void k_out(float* __restrict__ out) {
    const int tid = threadIdx.x;
    const int d = tid & 63;
    const int i = blockIdx.x * 4 + (tid >> 6);

    const float f1 = g_f1[i];
    const float t = -f1;               // high branch: f2 >= t
    const int b = binof(t);
    const int p0 = g_off[b], p1 = g_off[b + 1];

    float nh = 0.f, nl = 0.f, zh = 0.f, zl = 0.f;

    // boundary bin: exact per-element branch assignment
    for (int p = p0; p < p1; p++) {
        float v = g_f2s[p];
        float hv = g_h[g_perm[p] * DD + d];
        float eh = g_Eh[p], el = g_El[p];
        if (v >= t) { nh = fmaf(eh, hv, nh); zh += eh; }
        else        { nl = fmaf(el, hv, nl); zl += el; }
    }

    // high suffix: elements [p1, chunk end) + chunks + group table
    if (p1 < NN) {
        const int c1 = p1 >> 5, g1 = c1 >> 5;
        const int ce = (c1 + 1) << 5;
        for (int p = p1; p < ce; p++) {
            float eh = g_Eh[p];
            nh = fmaf(eh, g_h[g_perm[p] * DD + d], nh);
            zh += eh;
        }
        const int ge = (g1 + 1) << 5;
        for (int c = c1 + 1; c < ge; c++) {
            nh += g_ShC[c * DD + d];
            zh += g_ZhC[c];
        }
        nh += g_GsufH[(g1 + 1) * DD + d];
        zh += g_GsufZh[g1 + 1];
    }

    // low prefix: group table + chunks + elements [chunk start, p0)
    {
        const int c0 = p0 >> 5, g0 = c0 >> 5;
        const int cs = c0 << 5;
        for (int p = cs; p < p0; p++) {
            float el = g_El[p];
            nl = fmaf(el, g_h[g_perm[p] * DD + d], nl);
            zl += el;
        }
        const int gs = g0 << 5;
        for (int c = gs; c < c0; c++) {
            nl += g_SlC[c * DD + d];
            zl += g_ZlC[c];
        }
        nl += g_GpreL[g0 * DD + d];
        zl += g_GpreZl[g0];
    }

    const float u = f1 + MSTAB;
    const float cH = expf(fminf((1.f - LRALPHA) * u, 0.f));
    const float cL = expf(fminf(-(1.f - LRALPHA) * u, 0.f));

    const float den = cH * zh + cL * zl;
    const float num = cH * nh + cL * nl;
    const float r = num / den;

    out[i * DD + d] = (r > 0.f) ? r : expm1f(r);   // ELU (alpha=1)
}

// ---------------- launch ----------------
extern "C" void kernel_launch(void* const* d_in, const int* in_sizes, int n_in,
                              void* d_out, int out_size)
{
    const float* x  = (const float*)d_in[0];
    const float* Wt = (const float*)d_in[1];
    const float* a1 = (const float*)d_in[2];
    const float* b1 = (const float*)d_in[3];
    const float* a2 = (const float*)d_in[4];
    const float* b2 = (const float*)d_in[5];
    float* out = (float*)d_out;

    k_hf<<<NN / 16, 256>>>(x, Wt, a1, b1, a2, b2);
    k_binsort<<<1, 1024>>>();
    k_chunktot<<<NCHUNK, 256>>>();
    k_out<<<NN / 4, 256>>>(out);
}

// round 10
// speedup vs baseline: 1.3212x; 1.3212x over previous
#include <cuda_runtime.h>
#include <math.h>

#define NN 8192
#define DD 64
#define LRALPHA 0.2f
#define CHUNK 32
#define NCHUNK 256    // NN / CHUNK
#define NB 8192       // counting-sort bins
#define BR 8.0f       // fixed bin range [-BR, BR]
#define BININV 512.0f // NB / (2*BR)
#define MSTAB 8.0f    // softmax stabilizer (fixed bound; cancels exactly)
#define SCPAD 65

// ---------------- scratch (device globals; no allocation allowed) ----------------
__device__ float g_h[NN * DD];
__device__ float g_f1[NN];
__device__ float g_f2[NN];
__device__ float g_f2s[NN];             // f2 in bin-sorted order
__device__ int   g_perm[NN];            // sorted pos -> original row
__device__ float g_Eh[NN];              // exp(f2s - M)
__device__ float g_El[NN];              // exp(alpha*(f2s - M))
__device__ int g_cnt[NB];               // zero-init; k_binsort re-zeros each call
__device__ int g_off[NB + 1];
__device__ int g_tick;                  // grid-barrier; k_binsort re-zeros each call
__device__ float g_ShC[NCHUNK * DD];    // per-chunk totals Eh*h
__device__ float g_SlC[NCHUNK * DD];    // per-chunk totals El*h
__device__ float g_ZhC[NCHUNK];
__device__ float g_ZlC[NCHUNK];
__device__ float g_Sh[(NN + 1) * DD];   // global suffix sums of Eh*h
__device__ float g_Sl[(NN + 1) * DD];   // global exclusive prefix sums of El*h
__device__ float g_Zh[NN + 1];
__device__ float g_Zl[NN + 1];

__device__ __forceinline__ int binof(float v) {
    int b = (int)((v + BR) * BININV);
    return min(max(b, 0), NB - 1);
}

// ---------------- K1: h = x@Wt (Wt column in registers), f1, f2, histogram ----------------
__global__ void __launch_bounds__(256) k_hf(
    const float* __restrict__ x, const float* __restrict__ Wt,
    const float* __restrict__ a1, const float* __restrict__ b1,
    const float* __restrict__ a2, const float* __restrict__ b2)
{
    __shared__ float sx[4][DD];
    __shared__ float sP[4][2][2];
    const int tid = threadIdx.x;
    const int r = tid >> 6;
    const int d = tid & 63;
    const int lane = d & 31;
    const int half = d >> 5;

    float W[DD];
#pragma unroll
    for (int k = 0; k < DD; k++) W[k] = Wt[k * DD + d];
    const float va1 = a1[d], va2 = a2[d];

#pragma unroll
    for (int g = 0; g < 4; g++) {
        const int row = blockIdx.x * 16 + g * 4 + r;
        __syncthreads();
        sx[r][d] = x[row * DD + d];
        __syncthreads();
        float acc = 0.f;
#pragma unroll
        for (int k = 0; k < DD; k++) acc = fmaf(sx[r][k], W[k], acc);
        g_h[row * DD + d] = acc;
        float p1 = acc * va1, p2 = acc * va2;
#pragma unroll
        for (int s = 16; s > 0; s >>= 1) {
            p1 += __shfl_down_sync(0xffffffffu, p1, s);
            p2 += __shfl_down_sync(0xffffffffu, p2, s);
        }
        if (lane == 0) { sP[r][half][0] = p1; sP[r][half][1] = p2; }
        __syncthreads();
        if (d == 0) {
            float f1 = sP[r][0][0] + sP[r][1][0] + b1[0];
            float f2 = sP[r][0][1] + sP[r][1][1] + b2[0];
            g_f1[row] = f1;
            g_f2[row] = f2;
            atomicAdd(&g_cnt[binof(f2)], 1);
        }
    }
}

// ---------------- K2: bin scan + reset + scatter (f2, perm only; no exp) ----------------
__global__ void k_binsort() {
    __shared__ int sW[32];
    __shared__ int sFill[NB];           // 32 KB write cursors
    const int tid = threadIdx.x;
    const int base = tid * 8;

    int4 ca = *(const int4*)&g_cnt[base];
    int4 cb = *(const int4*)&g_cnt[base + 4];
    int c[8] = {ca.x, ca.y, ca.z, ca.w, cb.x, cb.y, cb.z, cb.w};
    int s = 0;
#pragma unroll
    for (int j = 0; j < 8; j++) s += c[j];
    const int lane = tid & 31, w = tid >> 5;
    int v = s;
#pragma unroll
    for (int o = 1; o < 32; o <<= 1) {
        int n = __shfl_up_sync(0xffffffffu, v, o);
        if (lane >= o) v += n;
    }
    if (lane == 31) sW[w] = v;
    __syncthreads();
    if (w == 0) {
        int wv = sW[lane];
#pragma unroll
        for (int o = 1; o < 32; o <<= 1) {
            int n = __shfl_up_sync(0xffffffffu, wv, o);
            if (lane >= o) wv += n;
        }
        sW[lane] = wv;
    }
    __syncthreads();
    int excl = v - s + (w > 0 ? sW[w - 1] : 0);
#pragma unroll
    for (int j = 0; j < 8; j++) {
        g_off[base + j] = excl;
        sFill[base + j] = excl;
        excl += c[j];
    }
    if (tid == 1023) g_off[NB] = excl;

    const int4 z4 = make_int4(0, 0, 0, 0);
    *(int4*)&g_cnt[base] = z4; *(int4*)&g_cnt[base + 4] = z4;
    if (tid == 0) g_tick = 0;           // reset grid barrier for k_scanchunk
    __syncthreads();

#pragma unroll
    for (int j = 0; j < 8; j++) {
        const int i = tid + j * 1024;
        float f2 = g_f2[i];
        int b = binof(f2);
        int pos = atomicAdd(&sFill[b], 1);
        g_perm[pos] = i;
        g_f2s[pos] = f2;
    }
}

// ---------------- K3: parallel per-chunk warp scans + grid barrier + global offsets ----------------
__global__ void __launch_bounds__(256) k_scanchunk() {
    __shared__ float sHv[CHUNK][SCPAD];
    __shared__ float sSh[CHUNK][SCPAD];
    __shared__ float sSl[CHUNK][SCPAD];
    __shared__ float sEh[CHUNK], sEl[CHUNK];
    __shared__ float sZh[CHUNK], sZl[CHUNK];
    __shared__ int   sPerm[CHUNK];
    __shared__ float sOffH[DD], sOffL[DD];
    __shared__ float sZOffH, sZOffL;

    const int tid = threadIdx.x;        // 256
    const int jj = tid >> 6;            // 0..3
    const int d = tid & 63;
    const int w = tid >> 5, lane = tid & 31;
    const int b = blockIdx.x;           // chunk id
    const int base = b * CHUNK;

    // warp 0: Eh/El + scalar Z scans (shuffle)
    if (tid < 32) {
        sPerm[tid] = g_perm[base + tid];
        float f = g_f2s[base + tid] - MSTAB;
        float eh = expf(f);
        float el = expf(LRALPHA * f);
        sEh[tid] = eh; sEl[tid] = el;
        g_Eh[base + tid] = eh; g_El[base + tid] = el;
        float vh = eh, vl = el;
#pragma unroll
        for (int o = 1; o < 32; o <<= 1) {
            float nh = __shfl_down_sync(0xffffffffu, vh, o);
            if (tid + o < 32) vh += nh;
            float nl = __shfl_up_sync(0xffffffffu, vl, o);
            if (tid >= o) vl += nl;
        }
        sZh[tid] = vh;                  // suffix-inclusive
        sZl[tid] = vl - el;             // exclusive prefix
        if (tid == 0)  g_ZhC[b] = vh;
        if (tid == 31) g_ZlC[b] = vl;
    }
    __syncthreads();

    // load 32x64 h tile (coalesced)
#pragma unroll
    for (int s = 0; s < 8; s++) {
        const int j = s * 4 + jj;
        sHv[j][d] = g_h[sPerm[j] * DD + d];
    }
    __syncthreads();

    // vector scans: warp w handles d = w*8 .. w*8+7; lanes = element index
#pragma unroll
    for (int dd = 0; dd < 8; dd++) {
        const int dc = w * 8 + dd;
        const float hv = sHv[lane][dc];
        const float ph = sEh[lane] * hv;
        const float pl = sEl[lane] * hv;
        float vh = ph, vl = pl;
#pragma unroll
        for (int o = 1; o < 32; o <<= 1) {
            float nh = __shfl_down_sync(0xffffffffu, vh, o);
            if (lane + o < 32) vh += nh;
            float nl = __shfl_up_sync(0xffffffffu, vl, o);
            if (lane >= o) vl += nl;
        }
        sSh[lane][dc] = vh;             // local suffix-inclusive
        sSl[lane][dc] = vl - pl;        // local exclusive prefix
        if (lane == 0)  g_ShC[b * DD + dc] = vh;   // chunk total H
        if (lane == 31) g_SlC[b * DD + dc] = vl;   // chunk total L
    }
    __threadfence();
    __syncthreads();

    // grid barrier (256 blocks, all wave-1 resident; g_tick reset by k_binsort)
    if (tid == 0) {
        atomicAdd(&g_tick, 1);
        while (*(volatile int*)&g_tick < NCHUNK) { }
    }
    __syncthreads();
    __threadfence();

    // cross-chunk offsets
    if (tid < 64) {                     // suffix over chunks > b
        float acc = 0.f;
        for (int c = b + 1; c < NCHUNK; c++) acc += g_ShC[c * DD + tid];
        sOffH[tid] = acc;
    } else if (tid < 128) {             // prefix over chunks < b
        float acc = 0.f;
        for (int c = 0; c < b; c++) acc += g_SlC[c * DD + (tid - 64)];
        sOffL[tid - 64] = acc;
    } else if (w == 4) {                // scalar zh suffix (warp-parallel)
        float acc = 0.f;
        for (int c = b + 1 + lane; c < NCHUNK; c += 32) acc += g_ZhC[c];
#pragma unroll
        for (int o = 16; o > 0; o >>= 1) acc += __shfl_down_sync(0xffffffffu, acc, o);
        if (lane == 0) sZOffH = acc;
    } else if (w == 5) {                // scalar zl prefix (warp-parallel)
        float acc = 0.f;
        for (int c = lane; c < b; c += 32) acc += g_ZlC[c];
#pragma unroll
        for (int o = 16; o > 0; o >>= 1) acc += __shfl_down_sync(0xffffffffu, acc, o);
        if (lane == 0) sZOffL = acc;
    }
    __syncthreads();

    // write globally-offset arrays (coalesced)
#pragma unroll
    for (int s = 0; s < 8; s++) {
        const int j = s * 4 + jj;
        g_Sh[(base + j) * DD + d] = sSh[j][d] + sOffH[d];
        g_Sl[(base + j) * DD + d] = sSl[j][d] + sOffL[d];
    }
    if (tid < 32) {
        g_Zh[base + tid] = sZh[tid] + sZOffH;
        g_Zl[base + tid] = sZl[tid] + sZOffL;
    }
    if (b == NCHUNK - 1) {              // index NN sentinels
        if (tid < 64) {
            g_Sh[NN * DD + tid] = 0.f;
            g_Sl[NN * DD + tid] = sOffL[tid] + g_SlC[b * DD + tid];
        }
        if (tid == 64) {
            g_Zh[NN] = 0.f;
            g_Zl[NN] = sZOffL + g_ZlC[b];
        }
    }
}

// ---------------- K4: per-row combine (boundary-bin exact scan + O(1) lookups) + ELU ----------------
__global__ void k_out(float* __restrict__ out) {
    const int tid = threadIdx.x;
    const int d = tid & 63;
    const int i = blockIdx.x * 4 + (tid >> 6);

    const float f1 = g_f1[i];
    const float t = -f1;                // high branch: f2 >= t
    const int b = binof(t);
    const int p0 = g_off[b], p1 = g_off[b + 1];

    // boundary bin: exact per-element branch assignment (avg ~1 element)
    float bh = 0.f, bl = 0.f, bzh = 0.f, bzl = 0.f;
    for (int p = p0; p < p1; p++) {
        float v = g_f2s[p];
        float hv = g_h[g_perm[p] * DD + d];
        float eh = g_Eh[p], el = g_El[p];
        if (v >= t) { bh = fmaf(eh, hv, bh); bzh += eh; }
        else        { bl = fmaf(el, hv, bl); bzl += el; }
    }

    const float u = f1 + MSTAB;
    const float cH = expf(fminf((1.f - LRALPHA) * u, 0.f));
    const float cL = expf(fminf(-(1.f - LRALPHA) * u, 0.f));

    const float den = cH * (g_Zh[p1] + bzh) + cL * (g_Zl[p0] + bzl);
    const float num = cH * (g_Sh[p1 * DD + d] + bh) + cL * (g_Sl[p0 * DD + d] + bl);
    const float r = num / den;

    out[i * DD + d] = (r > 0.f) ? r : expm1f(r);   // ELU (alpha=1)
}

// ---------------- launch ----------------
extern "C" void kernel_launch(void* const* d_in, const int* in_sizes, int n_in,
                              void* d_out, int out_size)
{
    const float* x  = (const float*)d_in[0];
    const float* Wt = (const float*)d_in[1];
    const float* a1 = (const float*)d_in[2];
    const float* b1 = (const float*)d_in[3];
    const float* a2 = (const float*)d_in[4];
    const float* b2 = (const float*)d_in[5];
    float* out = (float*)d_out;

    k_hf<<<NN / 16, 256>>>(x, Wt, a1, b1, a2, b2);
    k_binsort<<<1, 1024>>>();
    k_scanchunk<<<NCHUNK, 256>>>();
    k_out<<<NN / 4, 256>>>(out);
}

// round 12
// speedup vs baseline: 1.3686x; 1.0359x over previous
#include <cuda_runtime.h>
#include <math.h>

#define NN 8192
#define DD 64
#define LRALPHA 0.2f
#define CHUNK 32
#define NCHUNK 256    // NN / CHUNK
#define NB 8192       // counting-sort bins
#define BR 8.0f       // fixed bin range [-BR, BR]
#define BININV 512.0f // NB / (2*BR)
#define MSTAB 8.0f    // softmax stabilizer (fixed bound; cancels exactly)
#define SCPAD 65
#define NBLK 256      // persistent grid (2 blocks/SM on 148 SMs -> all resident)
#define NTHR 512

// ---------------- scratch (device globals; no allocation allowed) ----------------
__device__ float g_h[NN * DD];
__device__ float g_f1[NN];
__device__ float g_f2[NN];
__device__ float g_f2s[NN];
__device__ int   g_perm[NN];
__device__ float g_Eh[NN];
__device__ float g_El[NN];
__device__ int g_cnt[NB];               // zero-init; re-zeroed by owner block each call
__device__ int g_off[NB + 1];
__device__ int g_fill[NB];              // seeded with offsets each call before use
__device__ int g_bsum[NBLK];
__device__ unsigned g_arr;              // barrier arrive counter (self-resetting)
__device__ unsigned g_gen;              // barrier generation (monotone, never reset)
__device__ float g_ShC[NCHUNK * DD];
__device__ float g_SlC[NCHUNK * DD];
__device__ float g_ZhC[NCHUNK];
__device__ float g_ZlC[NCHUNK];
__device__ float g_Sh[(NN + 1) * DD];   // global suffix sums of Eh*h
__device__ float g_Sl[(NN + 1) * DD];   // global exclusive prefix sums of El*h
__device__ float g_Zh[NN + 1];
__device__ float g_Zl[NN + 1];

__device__ __forceinline__ int binof(float v) {
    int b = (int)((v + BR) * BININV);
    return min(max(b, 0), NB - 1);
}

// grid-wide barrier: self-resetting counter + monotone generation (replay-safe)
__device__ __forceinline__ void gridsync() {
    __syncthreads();
    if (threadIdx.x == 0) {
        __threadfence();                              // release phase writes
        unsigned gen0 = *(volatile unsigned*)&g_gen;  // pre-arrive generation
        unsigned old = atomicAdd(&g_arr, 1u);
        if (old == NBLK - 1) {
            atomicExch(&g_arr, 0u);                   // nobody spins on g_arr
            __threadfence();
            atomicAdd(&g_gen, 1u);                    // release
        } else {
            while (*(volatile unsigned*)&g_gen == gen0) { }
        }
        __threadfence();                              // acquire
    }
    __syncthreads();
}

// smem overlays
struct P1S {
    float Wt[DD * DD];
    float x[8][DD];
    float P[8][2][2];
};
struct P5S {
    float Hv[CHUNK][SCPAD], Sh[CHUNK][SCPAD], Sl[CHUNK][SCPAD];
    float Eh[CHUNK], El[CHUNK], Zh[CHUNK], Zl[CHUNK];
    int Perm[CHUNK];
    float OffH[DD], OffL[DD], ZOffH, ZOffL;
};
#define SMEM_BYTES (sizeof(P5S) > sizeof(P1S) ? sizeof(P5S) : sizeof(P1S))

__global__ void __launch_bounds__(NTHR, 2) k_fused(
    const float* __restrict__ x, const float* __restrict__ Wt,
    const float* __restrict__ a1, const float* __restrict__ b1,
    const float* __restrict__ a2, const float* __restrict__ b2,
    float* __restrict__ out)
{
    __shared__ __align__(16) char sraw[SMEM_BYTES];
    const int tid = threadIdx.x;
    const int b = blockIdx.x;
    const int r = tid >> 6;          // 0..7
    const int d = tid & 63;
    const int lane = d & 31;
    const int half = d >> 5;
    const int w = tid >> 5;          // warp id 0..15
    const int wl = tid & 31;

    // ================= P1: h = x@Wt, f1, f2, histogram (32 rows/block) =================
    {
        P1S& s1 = *reinterpret_cast<P1S*>(sraw);
        for (int i = tid; i < DD * DD; i += NTHR) s1.Wt[i] = Wt[i];
        const float va1 = a1[d], va2 = a2[d];
#pragma unroll
        for (int g = 0; g < 4; g++) {
            const int row = b * 32 + g * 8 + r;
            __syncthreads();
            s1.x[r][d] = x[row * DD + d];
            __syncthreads();
            float acc = 0.f;
#pragma unroll
            for (int k = 0; k < DD; k++) acc = fmaf(s1.x[r][k], s1.Wt[k * DD + d], acc);
            g_h[row * DD + d] = acc;
            float p1 = acc * va1, p2 = acc * va2;
#pragma unroll
            for (int s = 16; s > 0; s >>= 1) {
                p1 += __shfl_down_sync(0xffffffffu, p1, s);
                p2 += __shfl_down_sync(0xffffffffu, p2, s);
            }
            if (lane == 0) { s1.P[r][half][0] = p1; s1.P[r][half][1] = p2; }
            __syncthreads();
            if (d == 0) {
                float f1 = s1.P[r][0][0] + s1.P[r][1][0] + b1[0];
                float f2 = s1.P[r][0][1] + s1.P[r][1][1] + b2[0];
                g_f1[row] = f1;
                g_f2[row] = f2;
                atomicAdd(&g_cnt[binof(f2)], 1);
            }
        }
    }
    gridsync();   // GB1: histogram complete

    // ================= P2: per-block bin-count sums (own 32 bins) =================
    int mycnt = 0;
    if (tid < 32) {
        mycnt = g_cnt[b * 32 + tid];
        g_cnt[b * 32 + tid] = 0;              // reset for next replay
        int s = mycnt;
#pragma unroll
        for (int o = 16; o > 0; o >>= 1) s += __shfl_down_sync(0xffffffffu, s, o);
        if (tid == 0) g_bsum[b] = s;
    }
    gridsync();   // GB2: all block sums visible

    // ================= P3: bin offsets (base + warp scan); seed fill cursors =================
    if (tid < 32) {
        int base = 0;
        for (int j = tid; j < b; j += 32) base += g_bsum[j];
#pragma unroll
        for (int o = 16; o > 0; o >>= 1) base += __shfl_down_sync(0xffffffffu, base, o);
        base = __shfl_sync(0xffffffffu, base, 0);
        int v = mycnt;
#pragma unroll
        for (int o = 1; o < 32; o <<= 1) {
            int n = __shfl_up_sync(0xffffffffu, v, o);
            if (tid >= o) v += n;
        }
        int excl = base + v - mycnt;
        g_off[b * 32 + tid] = excl;
        g_fill[b * 32 + tid] = excl;
        if (b == NBLK - 1 && tid == 31) g_off[NB] = excl + mycnt;
    }
    gridsync();   // GB3: offsets + cursors visible

    // ================= P4: scatter (32 rows/block) + Eh/El =================
    if (tid < 32) {
        const int i = b * 32 + tid;
        float f2 = g_f2[i];
        int bin = binof(f2);
        int pos = atomicAdd(&g_fill[bin], 1);
        g_perm[pos] = i;
        g_f2s[pos] = f2;
        float f = f2 - MSTAB;
        g_Eh[pos] = expf(f);
        g_El[pos] = expf(LRALPHA * f);
    }
    gridsync();   // GB4: sorted arrays complete

    // ================= P5: chunk shuffle-scans + chunk totals =================
    P5S& s5 = *reinterpret_cast<P5S*>(sraw);
    const int base = b * CHUNK;
    if (tid < 32) {
        s5.Perm[tid] = g_perm[base + tid];
        float eh = g_Eh[base + tid], el = g_El[base + tid];
        s5.Eh[tid] = eh; s5.El[tid] = el;
        float vh = eh, vl = el;
#pragma unroll
        for (int o = 1; o < 32; o <<= 1) {
            float nh = __shfl_down_sync(0xffffffffu, vh, o);
            if (tid + o < 32) vh += nh;
            float nl = __shfl_up_sync(0xffffffffu, vl, o);
            if (tid >= o) vl += nl;
        }
        s5.Zh[tid] = vh;                 // suffix-inclusive
        s5.Zl[tid] = vl - el;            // exclusive prefix
        if (tid == 0)  g_ZhC[b] = vh;
        if (tid == 31) g_ZlC[b] = vl;
    }
    __syncthreads();
#pragma unroll
    for (int s = 0; s < 4; s++) {        // load 32x64 h tile, coalesced
        const int j = s * 8 + r;
        s5.Hv[j][d] = g_h[s5.Perm[j] * DD + d];
    }
    __syncthreads();
#pragma unroll
    for (int dd = 0; dd < 4; dd++) {     // warp w handles d-cols w*4..w*4+3
        const int dc = w * 4 + dd;
        const float hv = s5.Hv[wl][dc];
        const float ph = s5.Eh[wl] * hv;
        const float pl = s5.El[wl] * hv;
        float vh = ph, vl = pl;
#pragma unroll
        for (int o = 1; o < 32; o <<= 1) {
            float nh = __shfl_down_sync(0xffffffffu, vh, o);
            if (wl + o < 32) vh += nh;
            float nl = __shfl_up_sync(0xffffffffu, vl, o);
            if (wl >= o) vl += nl;
        }
        s5.Sh[wl][dc] = vh;              // local suffix-inclusive
        s5.Sl[wl][dc] = vl - pl;         // local exclusive prefix
        if (wl == 0)  g_ShC[b * DD + dc] = vh;
        if (wl == 31) g_SlC[b * DD + dc] = vl;
    }
    gridsync();   // GB5: all chunk totals visible

    // ---- cross-chunk offsets ----
    if (tid < 64) {                      // suffix over chunks > b
        float acc = 0.f;
        for (int c = b + 1; c < NCHUNK; c++) acc += g_ShC[c * DD + tid];
        s5.OffH[tid] = acc;
    } else if (tid < 128) {              // prefix over chunks < b
        float acc = 0.f;
        for (int c = 0; c < b; c++) acc += g_SlC[c * DD + (tid - 64)];
        s5.OffL[tid - 64] = acc;
    } else if (w == 4) {
        float acc = 0.f;
        for (int c = b + 1 + wl; c < NCHUNK; c += 32) acc += g_ZhC[c];
#pragma unroll
        for (int o = 16; o > 0; o >>= 1) acc += __shfl_down_sync(0xffffffffu, acc, o);
        if (wl == 0) s5.ZOffH = acc;
    } else if (w == 5) {
        float acc = 0.f;
        for (int c = wl; c < b; c += 32) acc += g_ZlC[c];
#pragma unroll
        for (int o = 16; o > 0; o >>= 1) acc += __shfl_down_sync(0xffffffffu, acc, o);
        if (wl == 0) s5.ZOffL = acc;
    }
    __syncthreads();

    // ---- write globally-offset arrays (+ sentinels) ----
#pragma unroll
    for (int s = 0; s < 4; s++) {
        const int j = s * 8 + r;
        g_Sh[(base + j) * DD + d] = s5.Sh[j][d] + s5.OffH[d];
        g_Sl[(base + j) * DD + d] = s5.Sl[j][d] + s5.OffL[d];
    }
    if (tid < 32) {
        g_Zh[base + tid] = s5.Zh[tid] + s5.ZOffH;
        g_Zl[base + tid] = s5.Zl[tid] + s5.ZOffL;
    }
    if (b == NCHUNK - 1) {
        if (tid < 64) {
            g_Sh[NN * DD + tid] = 0.f;
            g_Sl[NN * DD + tid] = s5.OffL[tid] + g_SlC[b * DD + tid];
        }
        if (tid == 64) {
            g_Zh[NN] = 0.f;
            g_Zl[NN] = s5.ZOffL + g_ZlC[b];
        }
    }
    gridsync();   // GB6: Sh/Sl/Zh/Zl complete

    // ================= P6: output (32 rows/block) =================
#pragma unroll
    for (int s = 0; s < 4; s++) {
        const int i = b * 32 + s * 8 + r;
        const float f1 = g_f1[i];
        const float t = -f1;             // high branch: f2 >= t
        const int bb = binof(t);
        const int p0 = g_off[bb], p1 = g_off[bb + 1];

        float bh = 0.f, bl = 0.f, bzh = 0.f, bzl = 0.f;
        for (int p = p0; p < p1; p++) {  // boundary bin, exact (avg ~1 elem)
            float v = g_f2s[p];
            float hv = g_h[g_perm[p] * DD + d];
            float eh = g_Eh[p], el = g_El[p];
            if (v >= t) { bh = fmaf(eh, hv, bh); bzh += eh; }
            else        { bl = fmaf(el, hv, bl); bzl += el; }
        }

        const float u = f1 + MSTAB;
        const float cH = expf(fminf((1.f - LRALPHA) * u, 0.f));
        const float cL = expf(fminf(-(1.f - LRALPHA) * u, 0.f));

        const float den = cH * (g_Zh[p1] + bzh) + cL * (g_Zl[p0] + bzl);
        const float num = cH * (g_Sh[p1 * DD + d] + bh) + cL * (g_Sl[p0 * DD + d] + bl);
        const float rr = num / den;

        out[i * DD + d] = (rr > 0.f) ? rr : expm1f(rr);   // ELU (alpha=1)
    }
}

// ---------------- launch ----------------
extern "C" void kernel_launch(void* const* d_in, const int* in_sizes, int n_in,
                              void* d_out, int out_size)
{
    const float* x  = (const float*)d_in[0];
    const float* Wt = (const float*)d_in[1];
    const float* a1 = (const float*)d_in[2];
    const float* b1 = (const float*)d_in[3];
    const float* a2 = (const float*)d_in[4];
    const float* b2 = (const float*)d_in[5];
    float* out = (float*)d_out;

    k_fused<<<NBLK, NTHR>>>(x, Wt, a1, b1, a2, b2, out);
}

// round 16
// speedup vs baseline: 1.3756x; 1.0052x over previous
#include <cuda_runtime.h>
#include <math.h>

#define NN 8192
#define DD 64
#define LRALPHA 0.2f
#define NBLK 256
#define NTHR 256
#define RPB 32              // rows per block
#define CHUNK 32
#define NCHUNK 256          // == NBLK
#define NB 32768            // counting-sort bins (center-bin occupancy ~1.6)
#define BPB 128             // bins per block = NB/NBLK
#define BR 8.0f
#define BININV 2048.0f      // NB/(2*BR)
#define MSTAB 8.0f          // softmax stabilizer (fixed; cancels exactly)

// ---------------- scratch (device globals; no allocation allowed) ----------------
__device__ __align__(16) float g_h[NN * DD];
__device__ float g_f1[NN];
__device__ float g_f2[NN];
__device__ float g_f2s[NN];
__device__ int   g_perm[NN];
__device__ float g_Eh[NN];
__device__ float g_El[NN];
__device__ int g_cnt[NB];               // zero-init; reset each call in P4
__device__ int g_off[NB + 1];
__device__ int g_fill[NB];              // seeded each call in P3
__device__ int g_bsum[NBLK];
__device__ unsigned g_arrG[16];         // tree barrier: group counters
__device__ unsigned g_arrTop;           // tree barrier: top counter
__device__ unsigned g_gen;              // generation (monotone, never reset)
__device__ float g_ShC[NCHUNK * DD];
__device__ float g_SlC[NCHUNK * DD];
__device__ float g_ZhC[NCHUNK];
__device__ float g_ZlC[NCHUNK];
__device__ __align__(16) float g_Sh[(NN + 1) * DD];  // global suffix sums Eh*h
__device__ __align__(16) float g_Sl[(NN + 1) * DD];  // global excl prefix sums El*h
__device__ float g_Zh[NN + 1];
__device__ float g_Zl[NN + 1];

__device__ __forceinline__ int binof(float v) {
    int b = (int)((v + BR) * BININV);
    return min(max(b, 0), NB - 1);
}

// grid barrier: 16x16 tree arrive + generation release, nanosleep-backoff spin
__device__ __forceinline__ void gridsync() {
    __threadfence();                     // all threads: release phase writes
    __syncthreads();
    if (threadIdx.x == 0) {
        unsigned gen0 = *(volatile unsigned*)&g_gen;
        unsigned l = atomicAdd(&g_arrG[blockIdx.x >> 4], 1u);
        if (l == 15u) {
            unsigned t = atomicAdd(&g_arrTop, 1u);
            if (t == 15u) {              // last block: reset + release
                *(volatile unsigned*)&g_arrTop = 0u;
#pragma unroll
                for (int g = 0; g < 16; g++) *(volatile unsigned*)&g_arrG[g] = 0u;
                __threadfence();
                atomicAdd(&g_gen, 1u);
            }
        }
        while (*(volatile unsigned*)&g_gen == gen0) __nanosleep(64);
        __threadfence();                 // acquire
    }
    __syncthreads();
}

// smem overlays
struct P1S {
    float xT[DD][RPB + 1];   // transposed x tile (pad 33)
    float W[DD * DD];
};
struct P5S {
    float Hv[CHUNK][DD + 1], Sh[CHUNK][DD + 1], Sl[CHUNK][DD + 1];
    float Eh[CHUNK], El[CHUNK], Zh[CHUNK], Zl[CHUNK];
    int Perm[CHUNK];
    float OffH[DD], OffL[DD], ZOffH, ZOffL;
};
#define SMEM_BYTES (sizeof(P5S) > sizeof(P1S) ? sizeof(P5S) : sizeof(P1S))

__global__ void __launch_bounds__(NTHR, 2) k_fused(
    const float* __restrict__ x, const float* __restrict__ Wt,
    const float* __restrict__ a1, const float* __restrict__ b1,
    const float* __restrict__ a2, const float* __restrict__ b2,
    float* __restrict__ out)
{
    __shared__ __align__(16) char sraw[SMEM_BYTES];
    __shared__ int sWsum[4];
    __shared__ int sBase;

    const int tid = threadIdx.x;
    const int b = blockIdx.x;
    const int tx = tid & 15, ty = tid >> 4;
    const int lane = tid & 31, w = tid >> 5;
    const int d = tid & 63, jr = tid >> 6;
    const int rowbase = b * RPB;

    // ========== P1: register-tiled GEMM (2x4 per thread) + f1/f2 + histogram ==========
    {
        P1S& s = *reinterpret_cast<P1S*>(sraw);
#pragma unroll
        for (int j = 0; j < 4; j++) {
            const int idx = (tid + j * 256) * 4;
            *(float4*)&s.W[idx] = *(const float4*)&Wt[idx];
        }
#pragma unroll
        for (int j = 0; j < 2; j++) {
            const int f = tid + j * 256;
            const int row = f >> 4, kq = f & 15;
            float4 v = *(const float4*)&x[(rowbase + row) * DD + kq * 4];
            s.xT[kq * 4 + 0][row] = v.x; s.xT[kq * 4 + 1][row] = v.y;
            s.xT[kq * 4 + 2][row] = v.z; s.xT[kq * 4 + 3][row] = v.w;
        }
        const float4 va1 = *(const float4*)&a1[tx * 4];
        const float4 va2 = *(const float4*)&a2[tx * 4];
        const float b1v = b1[0], b2v = b2[0];
        __syncthreads();

        const int R0 = ty * 2, R1 = R0 + 1;
        float acc0[4] = {0.f, 0.f, 0.f, 0.f};
        float acc1[4] = {0.f, 0.f, 0.f, 0.f};
#pragma unroll 16
        for (int k = 0; k < DD; k++) {
            const float a0 = s.xT[k][R0];
            const float a1r = s.xT[k][R1];
            const float4 w4 = *(float4*)&s.W[k * DD + tx * 4];
            acc0[0] = fmaf(a0, w4.x, acc0[0]); acc0[1] = fmaf(a0, w4.y, acc0[1]);
            acc0[2] = fmaf(a0, w4.z, acc0[2]); acc0[3] = fmaf(a0, w4.w, acc0[3]);
            acc1[0] = fmaf(a1r, w4.x, acc1[0]); acc1[1] = fmaf(a1r, w4.y, acc1[1]);
            acc1[2] = fmaf(a1r, w4.z, acc1[2]); acc1[3] = fmaf(a1r, w4.w, acc1[3]);
        }
        *(float4*)&g_h[(rowbase + R0) * DD + tx * 4] =
            make_float4(acc0[0], acc0[1], acc0[2], acc0[3]);
        *(float4*)&g_h[(rowbase + R1) * DD + tx * 4] =
            make_float4(acc1[0], acc1[1], acc1[2], acc1[3]);

        float p10 = acc0[0]*va1.x + acc0[1]*va1.y + acc0[2]*va1.z + acc0[3]*va1.w;
        float p20 = acc0[0]*va2.x + acc0[1]*va2.y + acc0[2]*va2.z + acc0[3]*va2.w;
        float p11 = acc1[0]*va1.x + acc1[1]*va1.y + acc1[2]*va1.z + acc1[3]*va1.w;
        float p21 = acc1[0]*va2.x + acc1[1]*va2.y + acc1[2]*va2.z + acc1[3]*va2.w;
#pragma unroll
        for (int o = 1; o < 16; o <<= 1) {       // reduce over tx (lane bits 0..3)
            p10 += __shfl_xor_sync(0xffffffffu, p10, o);
            p20 += __shfl_xor_sync(0xffffffffu, p20, o);
            p11 += __shfl_xor_sync(0xffffffffu, p11, o);
            p21 += __shfl_xor_sync(0xffffffffu, p21, o);
        }
        if (tx == 0) {
            const float f2a = p20 + b2v, f2b = p21 + b2v;
            g_f1[rowbase + R0] = p10 + b1v;
            g_f1[rowbase + R1] = p11 + b1v;
            g_f2[rowbase + R0] = f2a;
            g_f2[rowbase + R1] = f2b;
            atomicAdd(&g_cnt[binof(f2a)], 1);
            atomicAdd(&g_cnt[binof(f2b)], 1);
        }
    }
    gridsync();   // GB1: histogram complete

    // ========== P2: per-block bin sums (own 128 bins) ==========
    int cbin = 0, vscan = 0;
    if (tid < BPB) {
        cbin = g_cnt[b * BPB + tid];
        int sred = cbin;
#pragma unroll
        for (int o = 16; o > 0; o >>= 1) sred += __shfl_down_sync(0xffffffffu, sred, o);
        if (lane == 0) sWsum[w] = sred;
    }
    __syncthreads();
    if (tid == 0) g_bsum[b] = sWsum[0] + sWsum[1] + sWsum[2] + sWsum[3];
    gridsync();   // GB2: all block sums visible

    // ========== P3: bin offsets (base over blocks + local scan); seed cursors ==========
    if (tid < BPB) {
        vscan = cbin;
#pragma unroll
        for (int o = 1; o < 32; o <<= 1) {
            int n = __shfl_up_sync(0xffffffffu, vscan, o);
            if (lane >= o) vscan += n;
        }
        if (lane == 31) sWsum[w] = vscan;
    }
    if (w == 0) {
        int accb = 0;
        for (int j = lane; j < b; j += 32) accb += g_bsum[j];
#pragma unroll
        for (int o = 16; o > 0; o >>= 1) accb += __shfl_xor_sync(0xffffffffu, accb, o);
        if (lane == 0) sBase = accb;
    }
    __syncthreads();
    if (tid < BPB) {
        int woff = sBase;
        for (int q = 0; q < w; q++) woff += sWsum[q];
        const int excl = woff + vscan - cbin;
        g_off[b * BPB + tid] = excl;
        g_fill[b * BPB + tid] = excl;
        if (b == NBLK - 1 && tid == BPB - 1) g_off[NB] = excl + cbin;
    }
    gridsync();   // GB3: offsets + cursors visible

    // ========== P4: scatter (32 rows) + Eh/El; reset g_cnt ==========
    if (tid < RPB) {
        const int i = rowbase + tid;
        const float f2v = g_f2[i];
        const int bin = binof(f2v);
        const int pos = atomicAdd(&g_fill[bin], 1);
        g_perm[pos] = i;
        g_f2s[pos] = f2v;
        const float f = f2v - MSTAB;
        g_Eh[pos] = expf(f);
        g_El[pos] = expf(LRALPHA * f);
    }
    if (tid < BPB) g_cnt[b * BPB + tid] = 0;
    gridsync();   // GB4: sorted arrays complete

    // ========== P5: chunk shuffle-scans + chunk totals ==========
    P5S& s5 = *reinterpret_cast<P5S*>(sraw);
    const int cbase = b * CHUNK;
    if (tid < 32) {
        s5.Perm[tid] = g_perm[cbase + tid];
        const float eh = g_Eh[cbase + tid], el = g_El[cbase + tid];
        s5.Eh[tid] = eh; s5.El[tid] = el;
        float vh = eh, vl = el;
#pragma unroll
        for (int o = 1; o < 32; o <<= 1) {
            float nh = __shfl_down_sync(0xffffffffu, vh, o);
            if (tid + o < 32) vh += nh;
            float nl = __shfl_up_sync(0xffffffffu, vl, o);
            if (tid >= o) vl += nl;
        }
        s5.Zh[tid] = vh;                 // suffix-inclusive
        s5.Zl[tid] = vl - el;            // exclusive prefix
        if (tid == 0)  g_ZhC[b] = vh;
        if (tid == 31) g_ZlC[b] = vl;
    }
    __syncthreads();
#pragma unroll
    for (int sI = 0; sI < 8; sI++) {
        const int j = sI * 4 + jr;
        s5.Hv[j][d] = g_h[s5.Perm[j] * DD + d];
    }
    __syncthreads();
#pragma unroll
    for (int dd = 0; dd < 8; dd++) {     // warp w -> d-cols w*8..w*8+7; lanes = elements
        const int dc = w * 8 + dd;
        const float hv = s5.Hv[lane][dc];
        const float ph = s5.Eh[lane] * hv;
        const float pl = s5.El[lane] * hv;
        float vh = ph, vl = pl;
#pragma unroll
        for (int o = 1; o < 32; o <<= 1) {
            float nh = __shfl_down_sync(0xffffffffu, vh, o);
            if (lane + o < 32) vh += nh;
            float nl = __shfl_up_sync(0xffffffffu, vl, o);
            if (lane >= o) vl += nl;
        }
        s5.Sh[lane][dc] = vh;            // local suffix-inclusive
        s5.Sl[lane][dc] = vl - pl;       // local exclusive prefix
        if (lane == 0)  g_ShC[b * DD + dc] = vh;
        if (lane == 31) g_SlC[b * DD + dc] = vl;
    }
    gridsync();   // GB5: all chunk totals visible

    // ---- cross-chunk offsets + write globally-offset arrays ----
    if (tid < 64) {
        float acc = 0.f;
        for (int c2 = b + 1; c2 < NCHUNK; c2++) acc += g_ShC[c2 * DD + tid];
        s5.OffH[tid] = acc;
    } else if (tid < 128) {
        const int dq = tid - 64;
        float acc = 0.f;
        for (int c2 = 0; c2 < b; c2++) acc += g_SlC[c2 * DD + dq];
        s5.OffL[dq] = acc;
    } else if (w == 4) {
        float acc = 0.f;
        for (int c2 = b + 1 + lane; c2 < NCHUNK; c2 += 32) acc += g_ZhC[c2];
#pragma unroll
        for (int o = 16; o > 0; o >>= 1) acc += __shfl_down_sync(0xffffffffu, acc, o);
        if (lane == 0) s5.ZOffH = acc;
    } else if (w == 5) {
        float acc = 0.f;
        for (int c2 = lane; c2 < b; c2 += 32) acc += g_ZlC[c2];
#pragma unroll
        for (int o = 16; o > 0; o >>= 1) acc += __shfl_down_sync(0xffffffffu, acc, o);
        if (lane == 0) s5.ZOffL = acc;
    }
    __syncthreads();
#pragma unroll
    for (int sI = 0; sI < 8; sI++) {
        const int j = sI * 4 + jr;
        g_Sh[(cbase + j) * DD + d] = s5.Sh[j][d] + s5.OffH[d];
        g_Sl[(cbase + j) * DD + d] = s5.Sl[j][d] + s5.OffL[d];
    }
    if (tid < 32) {
        g_Zh[cbase + tid] = s5.Zh[tid] + s5.ZOffH;
        g_Zl[cbase + tid] = s5.Zl[tid] + s5.ZOffL;
    }
    if (b == NCHUNK - 1) {               // index-NN sentinels
        if (tid < 64) {
            g_Sh[NN * DD + tid] = 0.f;
            g_Sl[NN * DD + tid] = s5.OffL[tid] + g_SlC[b * DD + tid];
        }
        if (tid == 64) {
            g_Zh[NN] = 0.f;
            g_Zl[NN] = s5.ZOffL + g_ZlC[b];
        }
    }
    gridsync();   // GB6: Sh/Sl/Zh/Zl complete

    // ========== P6: output (32 rows; boundary bin ~1.6 elems avg) ==========
#pragma unroll 2
    for (int sI = 0; sI < 8; sI++) {
        const int i = rowbase + sI * 4 + jr;
        const float f1v = g_f1[i];
        const float t = -f1v;            // high branch: f2 >= t
        const int bb = binof(t);
        const int p0 = g_off[bb], p1 = g_off[bb + 1];

        float bh = 0.f, bl = 0.f, bzh = 0.f, bzl = 0.f;
        for (int p = p0; p < p1; p++) {  // boundary bin, exact
            const float v = g_f2s[p];
            const float hv = g_h[g_perm[p] * DD + d];
            const float eh = g_Eh[p], el = g_El[p];
            if (v >= t) { bh = fmaf(eh, hv, bh); bzh += eh; }
            else        { bl = fmaf(el, hv, bl); bzl += el; }
        }

        const float u = f1v + MSTAB;
        const float cH = expf(fminf((1.f - LRALPHA) * u, 0.f));
        const float cL = expf(fminf(-(1.f - LRALPHA) * u, 0.f));

        const float den = cH * (g_Zh[p1] + bzh) + cL * (g_Zl[p0] + bzl);
        const float num = cH * (g_Sh[p1 * DD + d] + bh) + cL * (g_Sl[p0 * DD + d] + bl);
        const float rr = num / den;

        out[i * DD + d] = (rr > 0.f) ? rr : expm1f(rr);   // ELU (alpha=1)
    }
}

// ---------------- launch ----------------
extern "C" void kernel_launch(void* const* d_in, const int* in_sizes, int n_in,
                              void* d_out, int out_size)
{
    const float* x  = (const float*)d_in[0];
    const float* Wt = (const float*)d_in[1];
    const float* a1 = (const float*)d_in[2];
    const float* b1 = (const float*)d_in[3];
    const float* a2 = (const float*)d_in[4];
    const float* b2 = (const float*)d_in[5];
    float* out = (float*)d_out;

    k_fused<<<NBLK, NTHR>>>(x, Wt, a1, b1, a2, b2, out);
}

// round 17
// speedup vs baseline: 1.4920x; 1.0846x over previous
#include <cuda_runtime.h>
#include <math.h>

#define NN 8192
#define DD 64
#define LRALPHA 0.2f
#define NBLK 128            // <= 148 SMs: exactly 1 block/SM, no stragglers
#define NTHR 1024
#define RPB 64              // rows per block
#define CHUNK 32
#define NCHUNK 256
#define CPB 2               // chunks per block
#define NB 32768            // counting-sort bins
#define BPB 256             // bins per block
#define BR 8.0f
#define BININV 2048.0f      // NB/(2*BR)
#define MSTAB 8.0f          // softmax stabilizer (fixed; cancels exactly)

// ---------------- scratch (device globals; no allocation allowed) ----------------
__device__ __align__(16) float g_h[NN * DD];
__device__ float g_f1[NN];
__device__ float g_f2[NN];
__device__ float g_f2s[NN];
__device__ int   g_perm[NN];
__device__ float g_Eh[NN];
__device__ float g_El[NN];
__device__ int g_cnt[NB];               // zero-init; owner block re-zeros each call
__device__ int g_off[NB + 1];
__device__ int g_fill[NB];              // seeded each call
__device__ unsigned g_arrG[8];          // tree barrier: 8 groups of 16 blocks
__device__ unsigned g_arrTop;
__device__ unsigned g_gen;              // generation (monotone, never reset)
__device__ float g_ShC[NCHUNK * DD];
__device__ float g_SlC[NCHUNK * DD];
__device__ float g_ZhC[NCHUNK];
__device__ float g_ZlC[NCHUNK];
__device__ __align__(16) float g_Sh[(NN + 1) * DD];
__device__ __align__(16) float g_Sl[(NN + 1) * DD];
__device__ float g_Zh[NN + 1];
__device__ float g_Zl[NN + 1];

__device__ __forceinline__ int binof(float v) {
    int b = (int)((v + BR) * BININV);
    return min(max(b, 0), NB - 1);
}

// grid barrier: 8x16 tree arrive + generation release; plain spin (1 blk/SM)
__device__ __forceinline__ void gridsync() {
    __threadfence();
    __syncthreads();
    if (threadIdx.x == 0) {
        const unsigned gen0 = *(volatile unsigned*)&g_gen;
        const unsigned l = atomicAdd(&g_arrG[blockIdx.x >> 4], 1u);
        if (l == 15u) {
            const unsigned t = atomicAdd(&g_arrTop, 1u);
            if (t == 7u) {
                *(volatile unsigned*)&g_arrTop = 0u;
#pragma unroll
                for (int g = 0; g < 8; g++) *(volatile unsigned*)&g_arrG[g] = 0u;
                __threadfence();
                atomicAdd(&g_gen, 1u);
            }
        }
        while (*(volatile unsigned*)&g_gen == gen0) { }
        __threadfence();
    }
    __syncthreads();
}

// ---------------- smem overlays ----------------
struct P1S {                 // GEMM phase
    float W[DD * DD];        // 16 KB
    float xT[DD][RPB + 1];   // 16.6 KB transposed x tile
};
struct P5H {                 // one chunk pipeline
    float HS[CHUNK][DD + 1]; // h tile; overwritten in-place by suffix scan
    float SL[CHUNK][DD + 1]; // prefix scan output
    float Eh[CHUNK], El[CHUNK], Zh[CHUNK], Zl[CHUNK];
    int   Perm[CHUNK];
    float OffH[DD], OffL[DD], ZOffH, ZOffL;
};
struct P5S { P5H h[2]; };
#define SMEM_BYTES (sizeof(P5S) > sizeof(P1S) ? sizeof(P5S) : sizeof(P1S))

__global__ void __launch_bounds__(NTHR, 1) k_fused(
    const float* __restrict__ x, const float* __restrict__ Wt,
    const float* __restrict__ a1, const float* __restrict__ b1,
    const float* __restrict__ a2, const float* __restrict__ b2,
    float* __restrict__ out)
{
    __shared__ __align__(16) char sraw[SMEM_BYTES];
    __shared__ int sWsum[32];
    __shared__ int sW8[8];
    __shared__ int sBase;

    const int tid = threadIdx.x;
    const int b = blockIdx.x;
    const int lane = tid & 31, w = tid >> 5;
    const int rowbase = b * RPB;

    // ========== P1: register-tiled GEMM (1 row x 4 cols/thread) + f1/f2 + histogram ==========
    {
        P1S& s = *reinterpret_cast<P1S*>(sraw);
        {   // load W (one float4 per thread)
            const int idx = tid * 4;
            *(float4*)&s.W[idx] = *(const float4*)&Wt[idx];
        }
        {   // load x transposed (one float4 per thread)
            const int row = tid >> 4, kq = tid & 15;
            float4 v = *(const float4*)&x[(rowbase + row) * DD + kq * 4];
            s.xT[kq * 4 + 0][row] = v.x; s.xT[kq * 4 + 1][row] = v.y;
            s.xT[kq * 4 + 2][row] = v.z; s.xT[kq * 4 + 3][row] = v.w;
        }
        const int tx = tid & 15, ty = tid >> 4;        // ty = row 0..63
        const float4 va1 = *(const float4*)&a1[tx * 4];
        const float4 va2 = *(const float4*)&a2[tx * 4];
        const float b1v = b1[0], b2v = b2[0];
        __syncthreads();

        float acc[4] = {0.f, 0.f, 0.f, 0.f};
#pragma unroll 16
        for (int k = 0; k < DD; k++) {
            const float a0 = s.xT[k][ty];
            const float4 w4 = *(float4*)&s.W[k * DD + tx * 4];
            acc[0] = fmaf(a0, w4.x, acc[0]); acc[1] = fmaf(a0, w4.y, acc[1]);
            acc[2] = fmaf(a0, w4.z, acc[2]); acc[3] = fmaf(a0, w4.w, acc[3]);
        }
        *(float4*)&g_h[(rowbase + ty) * DD + tx * 4] =
            make_float4(acc[0], acc[1], acc[2], acc[3]);

        float p1 = acc[0]*va1.x + acc[1]*va1.y + acc[2]*va1.z + acc[3]*va1.w;
        float p2 = acc[0]*va2.x + acc[1]*va2.y + acc[2]*va2.z + acc[3]*va2.w;
#pragma unroll
        for (int o = 1; o < 16; o <<= 1) {             // reduce over tx (lane bits 0..3)
            p1 += __shfl_xor_sync(0xffffffffu, p1, o);
            p2 += __shfl_xor_sync(0xffffffffu, p2, o);
        }
        if (tx == 0) {
            const float f2v = p2 + b2v;
            g_f1[rowbase + ty] = p1 + b1v;
            g_f2[rowbase + ty] = f2v;
            atomicAdd(&g_cnt[binof(f2v)], 1);
        }
    }
    gridsync();   // GB1: histogram complete

    // ========== P2: bin offsets (direct global base sum + local scan); seed cursors ==========
    {
        // global base: sum of all bins before this block's range
        int baseAcc = 0;
        for (int j = tid; j < b * BPB; j += NTHR) baseAcc += g_cnt[j];
#pragma unroll
        for (int o = 16; o > 0; o >>= 1) baseAcc += __shfl_down_sync(0xffffffffu, baseAcc, o);
        if (lane == 0) sWsum[w] = baseAcc;
        __syncthreads();
        if (w == 0) {
            int v = sWsum[lane];
#pragma unroll
            for (int o = 16; o > 0; o >>= 1) v += __shfl_down_sync(0xffffffffu, v, o);
            if (lane == 0) sBase = v;
        }
        // local exclusive scan over own 256 bins (8 warps)
        int cbin = 0, v = 0;
        if (tid < BPB) {
            cbin = g_cnt[b * BPB + tid];
            v = cbin;
#pragma unroll
            for (int o = 1; o < 32; o <<= 1) {
                int n = __shfl_up_sync(0xffffffffu, v, o);
                if (lane >= o) v += n;
            }
            if (lane == 31) sW8[w] = v;
        }
        __syncthreads();
        if (w == 0 && lane < 8) {
            int t = sW8[lane];
#pragma unroll
            for (int o = 1; o < 8; o <<= 1) {
                int n = __shfl_up_sync(0xffu, t, o);
                if (lane >= o) t += n;
            }
            sW8[lane] = t;
        }
        __syncthreads();
        if (tid < BPB) {
            const int excl = sBase + (v - cbin) + (w > 0 ? sW8[w - 1] : 0);
            g_off[b * BPB + tid] = excl;
            g_fill[b * BPB + tid] = excl;
        }
        if (b == 0 && tid == 0) g_off[NB] = NN;
    }
    gridsync();   // GB2: offsets + cursors visible

    // ========== P3: scatter (64 rows) + Eh/El; reset own g_cnt bins ==========
    if (tid < RPB) {
        const int i = rowbase + tid;
        const float f2v = g_f2[i];
        const int pos = atomicAdd(&g_fill[binof(f2v)], 1);
        g_perm[pos] = i;
        g_f2s[pos] = f2v;
        const float f = f2v - MSTAB;
        g_Eh[pos] = expf(f);
        g_El[pos] = expf(LRALPHA * f);
    }
    if (tid < BPB) g_cnt[b * BPB + tid] = 0;
    gridsync();   // GB3: sorted arrays complete

    // ========== P4: chunk shuffle-scans (2 chunks, one per half-block) ==========
    P5S& s5 = *reinterpret_cast<P5S*>(sraw);
    const int half = tid >> 9;           // 0 or 1
    const int htid = tid & 511;
    const int hw = htid >> 5;            // warp-in-half 0..15
    const int c = b * CPB + half;        // chunk id
    const int cbase = c * CHUNK;
    P5H& sh = s5.h[half];

    if (htid < 32) {
        sh.Perm[htid] = g_perm[cbase + htid];
        const float eh = g_Eh[cbase + htid], el = g_El[cbase + htid];
        sh.Eh[htid] = eh; sh.El[htid] = el;
        float vh = eh, vl = el;
#pragma unroll
        for (int o = 1; o < 32; o <<= 1) {
            float nh = __shfl_down_sync(0xffffffffu, vh, o);
            if (htid + o < 32) vh += nh;
            float nl = __shfl_up_sync(0xffffffffu, vl, o);
            if (htid >= o) vl += nl;
        }
        sh.Zh[htid] = vh;                // suffix-inclusive
        sh.Zl[htid] = vl - el;           // exclusive prefix
        if (htid == 0)  g_ZhC[c] = vh;
        if (htid == 31) g_ZlC[c] = vl;
    }
    __syncthreads();
    {
        const int d = htid & 63;
#pragma unroll
        for (int sI = 0; sI < 4; sI++) {     // load 32x64 h tile, coalesced
            const int j = sI * 8 + (htid >> 6);
            sh.HS[j][d] = g_h[sh.Perm[j] * DD + d];
        }
    }
    __syncthreads();
#pragma unroll
    for (int dd = 0; dd < 4; dd++) {         // warp hw -> d-cols hw*4..hw*4+3
        const int dc = hw * 4 + dd;
        const float hv = sh.HS[lane][dc];
        const float ph = sh.Eh[lane] * hv;
        const float pl = sh.El[lane] * hv;
        float vh = ph, vl = pl;
#pragma unroll
        for (int o = 1; o < 32; o <<= 1) {
            float nh = __shfl_down_sync(0xffffffffu, vh, o);
            if (lane + o < 32) vh += nh;
            float nl = __shfl_up_sync(0xffffffffu, vl, o);
            if (lane >= o) vl += nl;
        }
        sh.HS[lane][dc] = vh;                // in-place: suffix scan overwrites h
        sh.SL[lane][dc] = vl - pl;           // exclusive prefix
        if (lane == 0)  g_ShC[c * DD + dc] = vh;
        if (lane == 31) g_SlC[c * DD + dc] = vl;
    }
    gridsync();   // GB4: all chunk totals visible

    // ---- cross-chunk offsets + write globally-offset arrays ----
    if (htid < 64) {
        float acc = 0.f;
        for (int c2 = c + 1; c2 < NCHUNK; c2++) acc += g_ShC[c2 * DD + htid];
        sh.OffH[htid] = acc;
    } else if (htid < 128) {
        const int dq = htid - 64;
        float acc = 0.f;
        for (int c2 = 0; c2 < c; c2++) acc += g_SlC[c2 * DD + dq];
        sh.OffL[dq] = acc;
    } else if (hw == 4) {
        float acc = 0.f;
        for (int c2 = c + 1 + lane; c2 < NCHUNK; c2 += 32) acc += g_ZhC[c2];
#pragma unroll
        for (int o = 16; o > 0; o >>= 1) acc += __shfl_down_sync(0xffffffffu, acc, o);
        if (lane == 0) sh.ZOffH = acc;
    } else if (hw == 5) {
        float acc = 0.f;
        for (int c2 = lane; c2 < c; c2 += 32) acc += g_ZlC[c2];
#pragma unroll
        for (int o = 16; o > 0; o >>= 1) acc += __shfl_down_sync(0xffffffffu, acc, o);
        if (lane == 0) sh.ZOffL = acc;
    }
    __syncthreads();
    {
        const int d = htid & 63;
#pragma unroll
        for (int sI = 0; sI < 4; sI++) {
            const int j = sI * 8 + (htid >> 6);
            g_Sh[(cbase + j) * DD + d] = sh.HS[j][d] + sh.OffH[d];
            g_Sl[(cbase + j) * DD + d] = sh.SL[j][d] + sh.OffL[d];
        }
    }
    if (htid < 32) {
        g_Zh[cbase + htid] = sh.Zh[htid] + sh.ZOffH;
        g_Zl[cbase + htid] = sh.Zl[htid] + sh.ZOffL;
    }
    if (c == NCHUNK - 1) {                   // index-NN sentinels
        if (htid < 64) {
            g_Sh[NN * DD + htid] = 0.f;
            g_Sl[NN * DD + htid] = sh.OffL[htid] + g_SlC[c * DD + htid];
        }
        if (htid == 64) {
            g_Zh[NN] = 0.f;
            g_Zl[NN] = sh.ZOffL + g_ZlC[c];
        }
    }
    gridsync();   // GB5: Sh/Sl/Zh/Zl complete

    // ========== P5: output (64 rows; 16 rows x 64 d per iteration) ==========
    {
        const int d = tid & 63;
        const int rr = tid >> 6;             // 0..15
#pragma unroll
        for (int sI = 0; sI < 4; sI++) {
            const int i = rowbase + sI * 16 + rr;
            const float f1v = g_f1[i];
            const float t = -f1v;            // high branch: f2 >= t
            const int bb = binof(t);
            const int p0 = g_off[bb], p1 = g_off[bb + 1];

            float bh = 0.f, bl = 0.f, bzh = 0.f, bzl = 0.f;
            for (int p = p0; p < p1; p++) {  // boundary bin, exact
                const float v = g_f2s[p];
                const float hv = g_h[g_perm[p] * DD + d];
                const float eh = g_Eh[p], el = g_El[p];
                if (v >= t) { bh = fmaf(eh, hv, bh); bzh += eh; }
                else        { bl = fmaf(el, hv, bl); bzl += el; }
            }

            const float u = f1v + MSTAB;
            const float cH = expf(fminf((1.f - LRALPHA) * u, 0.f));
            const float cL = expf(fminf(-(1.f - LRALPHA) * u, 0.f));

            const float den = cH * (g_Zh[p1] + bzh) + cL * (g_Zl[p0] + bzl);
            const float num = cH * (g_Sh[p1 * DD + d] + bh) + cL * (g_Sl[p0 * DD + d] + bl);
            const float res = num / den;

            out[i * DD + d] = (res > 0.f) ? res : expm1f(res);   // ELU (alpha=1)
        }
    }
}

// ---------------- launch ----------------
extern "C" void kernel_launch(void* const* d_in, const int* in_sizes, int n_in,
                              void* d_out, int out_size)
{
    const float* x  = (const float*)d_in[0];
    const float* Wt = (const float*)d_in[1];
    const float* a1 = (const float*)d_in[2];
    const float* b1 = (const float*)d_in[3];
    const float* a2 = (const float*)d_in[4];
    const float* b2 = (const float*)d_in[5];
    float* out = (float*)d_out;

    k_fused<<<NBLK, NTHR>>>(x, Wt, a1, b1, a2, b2, out);
}